// round 1
// baseline (speedup 1.0000x reference)
#include <cuda_runtime.h>
#include <cstdint>

#define SVC_N  20000
#define INST_N 100000
#define NODE_N 10000
#define HID    128

#define E_SC_MAX 640000
#define E_IN_MAX 200000
#define E_NI_MAX 200000

// ---- count/rsqrt layout offsets (single concatenated buffer) ----
// A = svc->svc, B = inst->node, C = node->inst
#define OFF_A_S 0        // svc src deg   [20000]
#define OFF_A_D 20000    // svc dst deg   [20000]
#define OFF_B_S 40000    // inst src deg  [100000]
#define OFF_B_D 140000   // node dst deg  [10000]
#define OFF_C_S 150000   // node src deg  [10000]
#define OFF_C_D 160000   // inst dst deg  [100000]
#define CNT_TOTAL 260000

// ---- scratch (static device globals; no allocation at runtime) ----
__device__ int   g_cnt[CNT_TOTAL];
__device__ float g_rs[CNT_TOTAL];
__device__ int   g_offA[SVC_N + 1];
__device__ int   g_offB[NODE_N + 1];
__device__ int   g_offC[INST_N + 1];
__device__ int   g_curA[SVC_N];
__device__ int   g_curB[NODE_N];
__device__ int   g_curC[INST_N];
__device__ int   g_eA[E_SC_MAX];
__device__ int   g_eB[E_IN_MAX];
__device__ int   g_eC[E_NI_MAX];
__device__ int   g_bsum[1024];
__device__ float g_aggA[(size_t)SVC_N * HID];
__device__ float g_aggB[(size_t)NODE_N * HID];
__device__ float g_hC[(size_t)NODE_N * HID];

// ============================================================================
// Degree histogram: one pass over an edge list updates src & dst counts.
// ============================================================================
__global__ void hist_k(const int* __restrict__ src, const int* __restrict__ dst,
                       int E, int* __restrict__ cs, int* __restrict__ cd) {
    int i = blockIdx.x * blockDim.x + threadIdx.x;
    if (i < E) {
        atomicAdd(&cs[src[i]], 1);
        atomicAdd(&cd[dst[i]], 1);
    }
}

__global__ void rsqrt_k(const int* __restrict__ cnt, float* __restrict__ rs, int n) {
    int i = blockIdx.x * blockDim.x + threadIdx.x;
    if (i < n) {
        int c = cnt[i];
        rs[i] = rsqrtf((float)(c > 0 ? c : 1));
    }
}

// ============================================================================
// Exclusive scan (3-kernel): block scan -> scan of block sums -> add.
// ============================================================================
__global__ void scan_block_k(const int* __restrict__ in, int n,
                             int* __restrict__ out_excl, int* __restrict__ bsums) {
    __shared__ int s[1024];
    int tid = threadIdx.x;
    int gid = blockIdx.x * 1024 + tid;
    int v = (gid < n) ? in[gid] : 0;
    s[tid] = v;
    __syncthreads();
    for (int off = 1; off < 1024; off <<= 1) {
        int t = (tid >= off) ? s[tid - off] : 0;
        __syncthreads();
        s[tid] += t;
        __syncthreads();
    }
    if (gid < n) out_excl[gid] = s[tid] - v;
    if (tid == 1023) bsums[blockIdx.x] = s[1023];
}

__global__ void scan_bsums_k(int* __restrict__ bsums, int nb) {
    __shared__ int s[1024];
    int tid = threadIdx.x;
    int v = (tid < nb) ? bsums[tid] : 0;
    s[tid] = v;
    __syncthreads();
    for (int off = 1; off < 1024; off <<= 1) {
        int t = (tid >= off) ? s[tid - off] : 0;
        __syncthreads();
        s[tid] += t;
        __syncthreads();
    }
    if (tid < nb) bsums[tid] = s[tid] - v;  // exclusive
}

__global__ void scan_add_k(int* __restrict__ off_arr, const int* __restrict__ bsums,
                           int n, int E, int* __restrict__ cur) {
    int gid = blockIdx.x * 1024 + threadIdx.x;
    if (gid < n) {
        int o = off_arr[gid] + bsums[blockIdx.x];
        off_arr[gid] = o;
        cur[gid] = o;
    }
    if (gid == 0) off_arr[n] = E;
}

// ============================================================================
// Scatter edges into dst-CSR (stores src index per slot).
// ============================================================================
__global__ void scatter_k(const int* __restrict__ src, const int* __restrict__ dst,
                          int E, int* __restrict__ cur, int* __restrict__ elist) {
    int i = blockIdx.x * blockDim.x + threadIdx.x;
    if (i < E) {
        int p = atomicAdd(&cur[dst[i]], 1);
        elist[p] = src[i];
    }
}

// ============================================================================
// Aggregation: one warp per dst row, gather 128-float source rows and sum.
// PRESCALE: multiply each gathered row by rs_s[src] (deg_src^-1/2).
// EPI: out = leaky(acc * rs_d[dst] + bias)  (final output rows).
// ============================================================================
template <bool PRESCALE, bool EPI>
__global__ void __launch_bounds__(256) agg_k(
    const float* __restrict__ feat, const float* __restrict__ rs_s,
    const int* __restrict__ off, const int* __restrict__ elist,
    const float* __restrict__ rs_d, const float* __restrict__ bias,
    float* __restrict__ out, int ndst) {
    int warp = (blockIdx.x * blockDim.x + threadIdx.x) >> 5;
    int lane = threadIdx.x & 31;
    if (warp >= ndst) return;
    int b0 = off[warp];
    int b1 = off[warp + 1];
    float4 acc = make_float4(0.f, 0.f, 0.f, 0.f);
    for (int e = b0; e < b1; e++) {
        int s = elist[e];
        float4 v = __ldg((const float4*)(feat + (size_t)s * HID) + lane);
        if (PRESCALE) {
            float r = __ldg(rs_s + s);
            v.x *= r; v.y *= r; v.z *= r; v.w *= r;
        }
        acc.x += v.x; acc.y += v.y; acc.z += v.z; acc.w += v.w;
    }
    if (EPI) {
        float rd = rs_d[warp];
        float4 bb = __ldg((const float4*)bias + lane);
        acc.x = acc.x * rd + bb.x;
        acc.y = acc.y * rd + bb.y;
        acc.z = acc.z * rd + bb.z;
        acc.w = acc.w * rd + bb.w;
        acc.x = acc.x >= 0.f ? acc.x : 0.01f * acc.x;
        acc.y = acc.y >= 0.f ? acc.y : 0.01f * acc.y;
        acc.z = acc.z >= 0.f ? acc.z : 0.01f * acc.z;
        acc.w = acc.w >= 0.f ? acc.w : 0.01f * acc.w;
    }
    ((float4*)(out + (size_t)warp * HID))[lane] = acc;
}

// ============================================================================
// GEMM: out[n,128] = A[n,128] @ W[128,128], fp32 SIMT.
// Tile: 32 rows x 128 cols per block, 256 threads, 4x4 register blocking.
// PRESCALE: A row r scaled by rs_s[r] on smem load.
// EPI: out = leaky(acc * rs_d[row] + bias[col]).
// Dynamic smem: As 32x128 (16KB) + Ws 128x128 (64KB) = 80KB.
// ============================================================================
template <bool PRESCALE, bool EPI>
__global__ void __launch_bounds__(256) gemm_k(
    const float* __restrict__ A, const float* __restrict__ W,
    const float* __restrict__ rs_s, const float* __restrict__ rs_d,
    const float* __restrict__ bias, float* __restrict__ out, int n) {
    extern __shared__ float sm[];
    float* As = sm;                // [32][128]
    float* Ws = sm + 32 * 128;     // [128][128]
    int tid = threadIdx.x;
    int base = blockIdx.x * 32;

    for (int i = tid; i < 128 * 128; i += 256) Ws[i] = W[i];
    for (int i = tid; i < 32 * 128; i += 256) {
        int r = i >> 7, k = i & 127;
        int gr = base + r;
        float v = 0.f;
        if (gr < n) {
            v = A[(size_t)gr * HID + k];
            if (PRESCALE) v *= rs_s[gr];
        }
        As[i] = v;
    }
    __syncthreads();

    int tx = tid & 31;   // col group: cols 4*tx..4*tx+3
    int ty = tid >> 5;   // row group: rows 4*ty..4*ty+3
    float acc[4][4] = {};

#pragma unroll 8
    for (int k = 0; k < 128; k++) {
        float a0 = As[(ty * 4 + 0) * 128 + k];
        float a1 = As[(ty * 4 + 1) * 128 + k];
        float a2 = As[(ty * 4 + 2) * 128 + k];
        float a3 = As[(ty * 4 + 3) * 128 + k];
        float4 w = *(const float4*)&Ws[k * 128 + tx * 4];
        acc[0][0] += a0 * w.x; acc[0][1] += a0 * w.y; acc[0][2] += a0 * w.z; acc[0][3] += a0 * w.w;
        acc[1][0] += a1 * w.x; acc[1][1] += a1 * w.y; acc[1][2] += a1 * w.z; acc[1][3] += a1 * w.w;
        acc[2][0] += a2 * w.x; acc[2][1] += a2 * w.y; acc[2][2] += a2 * w.z; acc[2][3] += a2 * w.w;
        acc[3][0] += a3 * w.x; acc[3][1] += a3 * w.y; acc[3][2] += a3 * w.z; acc[3][3] += a3 * w.w;
    }

#pragma unroll
    for (int r = 0; r < 4; r++) {
        int gr = base + ty * 4 + r;
        if (gr >= n) continue;
        float4 o;
        if (EPI) {
            float rd = rs_d[gr];
            float4 bb = *(const float4*)&bias[tx * 4];
            o.x = acc[r][0] * rd + bb.x;
            o.y = acc[r][1] * rd + bb.y;
            o.z = acc[r][2] * rd + bb.z;
            o.w = acc[r][3] * rd + bb.w;
            o.x = o.x >= 0.f ? o.x : 0.01f * o.x;
            o.y = o.y >= 0.f ? o.y : 0.01f * o.y;
            o.z = o.z >= 0.f ? o.z : 0.01f * o.z;
            o.w = o.w >= 0.f ? o.w : 0.01f * o.w;
        } else {
            o.x = acc[r][0]; o.y = acc[r][1]; o.z = acc[r][2]; o.w = acc[r][3];
        }
        *(float4*)&out[(size_t)gr * HID + tx * 4] = o;
    }
}

// ============================================================================
// Host launch
// ============================================================================
static void run_scan(const int* cnt_d, int n, int* off, int* cur, int E, int* bsum) {
    int nb = (n + 1023) / 1024;
    scan_block_k<<<nb, 1024>>>(cnt_d, n, off, bsum);
    scan_bsums_k<<<1, 1024>>>(bsum, nb);
    scan_add_k<<<nb, 1024>>>(off, bsum, n, E, cur);
}

extern "C" void kernel_launch(void* const* d_in, const int* in_sizes, int n_in,
                              void* d_out, int out_size) {
    const float* svc_feat  = (const float*)d_in[0];
    const float* inst_feat = (const float*)d_in[1];
    const float* node_feat = (const float*)d_in[2];
    const float* W_svc  = (const float*)d_in[3];
    const float* b_svc  = (const float*)d_in[4];
    const float* W_inst = (const float*)d_in[5];
    const float* b_inst = (const float*)d_in[6];
    const float* W_node = (const float*)d_in[7];
    const float* b_node = (const float*)d_in[8];
    const int* sc_src = (const int*)d_in[9];
    const int* sc_dst = (const int*)d_in[10];
    const int* in_src = (const int*)d_in[11];
    const int* in_dst = (const int*)d_in[12];
    const int* ni_src = (const int*)d_in[13];
    const int* ni_dst = (const int*)d_in[14];
    float* out = (float*)d_out;

    int E_sc = in_sizes[9];
    int E_in = in_sizes[11];
    int E_ni = in_sizes[13];

    int *cnt, *offA, *offB, *offC, *curA, *curB, *curC, *eA, *eB, *eC, *bsum;
    float *rs, *aggA, *aggB, *hC;
    cudaGetSymbolAddress((void**)&cnt, g_cnt);
    cudaGetSymbolAddress((void**)&rs, g_rs);
    cudaGetSymbolAddress((void**)&offA, g_offA);
    cudaGetSymbolAddress((void**)&offB, g_offB);
    cudaGetSymbolAddress((void**)&offC, g_offC);
    cudaGetSymbolAddress((void**)&curA, g_curA);
    cudaGetSymbolAddress((void**)&curB, g_curB);
    cudaGetSymbolAddress((void**)&curC, g_curC);
    cudaGetSymbolAddress((void**)&eA, g_eA);
    cudaGetSymbolAddress((void**)&eB, g_eB);
    cudaGetSymbolAddress((void**)&eC, g_eC);
    cudaGetSymbolAddress((void**)&bsum, g_bsum);
    cudaGetSymbolAddress((void**)&aggA, g_aggA);
    cudaGetSymbolAddress((void**)&aggB, g_aggB);
    cudaGetSymbolAddress((void**)&hC, g_hC);

    const int SMEM = (32 * 128 + 128 * 128) * 4;  // 80KB
    cudaFuncSetAttribute(gemm_k<true, false>, cudaFuncAttributeMaxDynamicSharedMemorySize, SMEM);
    cudaFuncSetAttribute(gemm_k<false, true>, cudaFuncAttributeMaxDynamicSharedMemorySize, SMEM);

    // 1) degrees
    cudaMemsetAsync(cnt, 0, CNT_TOTAL * sizeof(int));
    hist_k<<<(E_sc + 255) / 256, 256>>>(sc_src, sc_dst, E_sc, cnt + OFF_A_S, cnt + OFF_A_D);
    hist_k<<<(E_in + 255) / 256, 256>>>(in_src, in_dst, E_in, cnt + OFF_B_S, cnt + OFF_B_D);
    hist_k<<<(E_ni + 255) / 256, 256>>>(ni_src, ni_dst, E_ni, cnt + OFF_C_S, cnt + OFF_C_D);
    rsqrt_k<<<(CNT_TOTAL + 255) / 256, 256>>>(cnt, rs, CNT_TOTAL);

    // 2) dst-CSR build
    run_scan(cnt + OFF_A_D, SVC_N, offA, curA, E_sc, bsum);
    run_scan(cnt + OFF_B_D, NODE_N, offB, curB, E_in, bsum);
    run_scan(cnt + OFF_C_D, INST_N, offC, curC, E_ni, bsum);
    scatter_k<<<(E_sc + 255) / 256, 256>>>(sc_src, sc_dst, E_sc, curA, eA);
    scatter_k<<<(E_in + 255) / 256, 256>>>(in_src, in_dst, E_in, curB, eB);
    scatter_k<<<(E_ni + 255) / 256, 256>>>(ni_src, ni_dst, E_ni, curC, eC);

    // 3) conv C (node->inst): GEMM first on the small (node) side
    gemm_k<true, false><<<(NODE_N + 31) / 32, 256, SMEM>>>(
        node_feat, W_node, rs + OFF_C_S, nullptr, nullptr, hC, NODE_N);

    // 4) aggregations
    agg_k<true, false><<<((size_t)SVC_N * 32 + 255) / 256, 256>>>(
        svc_feat, rs + OFF_A_S, offA, eA, nullptr, nullptr, aggA, SVC_N);
    agg_k<true, false><<<((size_t)NODE_N * 32 + 255) / 256, 256>>>(
        inst_feat, rs + OFF_B_S, offB, eB, nullptr, nullptr, aggB, NODE_N);
    agg_k<false, true><<<((size_t)INST_N * 32 + 255) / 256, 256>>>(
        hC, nullptr, offC, eC, rs + OFF_C_D, b_node, out + (size_t)NODE_N * HID, INST_N);

    // 5) conv A & B GEMMs with fused norm/bias/leaky epilogue
    gemm_k<false, true><<<(NODE_N + 31) / 32, 256, SMEM>>>(
        aggB, W_inst, nullptr, rs + OFF_B_D, b_inst, out, NODE_N);
    gemm_k<false, true><<<(SVC_N + 31) / 32, 256, SMEM>>>(
        aggA, W_svc, nullptr, rs + OFF_A_D, b_svc,
        out + (size_t)(NODE_N + INST_N) * HID, SVC_N);
}

// round 2
// speedup vs baseline: 1.2544x; 1.2544x over previous
#include <cuda_runtime.h>
#include <cstdint>

#define SVC_N  20000
#define INST_N 100000
#define NODE_N 10000
#define HID    128

#define E_SC_MAX 640000
#define E_IN_MAX 200000
#define E_NI_MAX 200000

// ---- count/rsqrt layout offsets (single concatenated buffer) ----
// A = svc->svc, B = inst->node, C = node->inst
#define OFF_A_S 0        // svc src deg   [20000]
#define OFF_A_D 20000    // svc dst deg   [20000]
#define OFF_B_S 40000    // inst src deg  [100000]
#define OFF_B_D 140000   // node dst deg  [10000]
#define OFF_C_S 150000   // node src deg  [10000]
#define OFF_C_D 160000   // inst dst deg  [100000]
#define CNT_TOTAL 260000

// scan block counts (1024 elems per block)
#define NB_A 20   // ceil(20000/1024)
#define NB_B 10   // ceil(10000/1024)
#define NB_C 98   // ceil(100000/1024)
#define NB_TOTAL (NB_A + NB_B + NB_C)   // 128

// bsum segment offsets
#define BS_A 0
#define BS_B 128
#define BS_C 256

// ---- scratch (static device globals; no allocation at runtime) ----
__device__ int   g_cnt[CNT_TOTAL];
__device__ float g_rs[CNT_TOTAL];
__device__ int   g_offA[SVC_N + 1];
__device__ int   g_offB[NODE_N + 1];
__device__ int   g_offC[INST_N + 1];
__device__ int   g_curA[SVC_N];
__device__ int   g_curB[NODE_N];
__device__ int   g_curC[INST_N];
__device__ int   g_eA[E_SC_MAX];
__device__ int   g_eB[E_IN_MAX];
__device__ int   g_eC[E_NI_MAX];
__device__ int   g_bsum[1024];
__device__ float g_aggA[(size_t)SVC_N * HID];
__device__ float g_aggB[(size_t)NODE_N * HID];
__device__ float g_hC[(size_t)NODE_N * HID];

// ============================================================================
// Fused degree histogram over all 3 edge lists (one launch).
// ============================================================================
__global__ void hist_all_k(const int* __restrict__ sA, const int* __restrict__ dA, int eA,
                           const int* __restrict__ sB, const int* __restrict__ dB, int eB,
                           const int* __restrict__ sC, const int* __restrict__ dC, int eC,
                           int* __restrict__ cnt) {
    int i = blockIdx.x * blockDim.x + threadIdx.x;
    if (i < eA) {
        atomicAdd(&cnt[OFF_A_S + sA[i]], 1);
        atomicAdd(&cnt[OFF_A_D + dA[i]], 1);
    } else if (i < eA + eB) {
        int j = i - eA;
        atomicAdd(&cnt[OFF_B_S + sB[j]], 1);
        atomicAdd(&cnt[OFF_B_D + dB[j]], 1);
    } else if (i < eA + eB + eC) {
        int j = i - eA - eB;
        atomicAdd(&cnt[OFF_C_S + sC[j]], 1);
        atomicAdd(&cnt[OFF_C_D + dC[j]], 1);
    }
}

__global__ void rsqrt_k(const int* __restrict__ cnt, float* __restrict__ rs, int n) {
    int i = blockIdx.x * blockDim.x + threadIdx.x;
    if (i < n) {
        int c = cnt[i];
        rs[i] = rsqrtf((float)(c > 0 ? c : 1));
    }
}

// ============================================================================
// Fused exclusive scan over the 3 dst-degree arrays (3 launches total).
// Block -> (array segment, chunk) mapping is compile-time.
// ============================================================================
__device__ __forceinline__ int block_scan_1024(int* s, int tid, int v) {
    s[tid] = v;
    __syncthreads();
    for (int off = 1; off < 1024; off <<= 1) {
        int t = (tid >= off) ? s[tid - off] : 0;
        __syncthreads();
        s[tid] += t;
        __syncthreads();
    }
    return s[tid];   // inclusive
}

__global__ void scan_block_all_k(const int* __restrict__ cnt,
                                 int* __restrict__ offA, int* __restrict__ offB,
                                 int* __restrict__ offC, int* __restrict__ bs) {
    __shared__ int s[1024];
    int bid = blockIdx.x, tid = threadIdx.x;
    const int* in; int n; int* out; int* bsum; int chunk;
    if (bid < NB_A)              { in = cnt + OFF_A_D; n = SVC_N;  out = offA; bsum = bs + BS_A; chunk = bid; }
    else if (bid < NB_A + NB_B)  { in = cnt + OFF_B_D; n = NODE_N; out = offB; bsum = bs + BS_B; chunk = bid - NB_A; }
    else                         { in = cnt + OFF_C_D; n = INST_N; out = offC; bsum = bs + BS_C; chunk = bid - NB_A - NB_B; }
    int gid = chunk * 1024 + tid;
    int v = (gid < n) ? in[gid] : 0;
    int inc = block_scan_1024(s, tid, v);
    if (gid < n) out[gid] = inc - v;
    if (tid == 1023) bsum[chunk] = inc;
}

__global__ void scan_bsums_all_k(int* __restrict__ bs) {
    __shared__ int s[1024];
    int tid = threadIdx.x;
    int* seg; int nb;
    if (blockIdx.x == 0)      { seg = bs + BS_A; nb = NB_A; }
    else if (blockIdx.x == 1) { seg = bs + BS_B; nb = NB_B; }
    else                      { seg = bs + BS_C; nb = NB_C; }
    int v = (tid < nb) ? seg[tid] : 0;
    int inc = block_scan_1024(s, tid, v);
    if (tid < nb) seg[tid] = inc - v;   // exclusive
}

__global__ void scan_add_all_k(int* __restrict__ offA, int* __restrict__ offB,
                               int* __restrict__ offC, const int* __restrict__ bs,
                               int* __restrict__ curA, int* __restrict__ curB,
                               int* __restrict__ curC,
                               int eA, int eB, int eC) {
    int bid = blockIdx.x, tid = threadIdx.x;
    int* out; const int* bsum; int n, E, chunk; int* cur;
    if (bid < NB_A)              { out = offA; bsum = bs + BS_A; n = SVC_N;  E = eA; chunk = bid;               cur = curA; }
    else if (bid < NB_A + NB_B)  { out = offB; bsum = bs + BS_B; n = NODE_N; E = eB; chunk = bid - NB_A;        cur = curB; }
    else                         { out = offC; bsum = bs + BS_C; n = INST_N; E = eC; chunk = bid - NB_A - NB_B; cur = curC; }
    int gid = chunk * 1024 + tid;
    if (gid < n) {
        int o = out[gid] + bsum[chunk];
        out[gid] = o;
        cur[gid] = o;
    }
    if (chunk == 0 && tid == 0) out[n] = E;
}

// ============================================================================
// Fused scatter into dst-CSR (stores src index per slot), all 3 edge lists.
// ============================================================================
__global__ void scatter_all_k(const int* __restrict__ sA, const int* __restrict__ dA, int eA,
                              const int* __restrict__ sB, const int* __restrict__ dB, int eB,
                              const int* __restrict__ sC, const int* __restrict__ dC, int eC,
                              int* __restrict__ curA, int* __restrict__ curB, int* __restrict__ curC,
                              int* __restrict__ elA, int* __restrict__ elB, int* __restrict__ elC) {
    int i = blockIdx.x * blockDim.x + threadIdx.x;
    if (i < eA) {
        int p = atomicAdd(&curA[dA[i]], 1);
        elA[p] = sA[i];
    } else if (i < eA + eB) {
        int j = i - eA;
        int p = atomicAdd(&curB[dB[j]], 1);
        elB[p] = sB[j];
    } else if (i < eA + eB + eC) {
        int j = i - eA - eB;
        int p = atomicAdd(&curC[dC[j]], 1);
        elC[p] = sC[j];
    }
}

// ============================================================================
// Combined aggregation: one warp per dst row across ALL three convs.
//   seg A: svc agg    (prescale rs_src, plain store to aggA)
//   seg B: node agg   (prescale rs_src, plain store to aggB)
//   seg C: inst rows  (gather pre-transformed hC, fused norm+bias+leaky -> out)
// ============================================================================
__global__ void __launch_bounds__(256) agg_all_k(
    const float* __restrict__ svc_feat, const float* __restrict__ inst_feat,
    const float* __restrict__ hC, const float* __restrict__ rs,
    const int* __restrict__ offA, const int* __restrict__ elA,
    const int* __restrict__ offB, const int* __restrict__ elB,
    const int* __restrict__ offC, const int* __restrict__ elC,
    const float* __restrict__ b_node, float* __restrict__ aggA,
    float* __restrict__ aggB, float* __restrict__ out_inst) {
    int w = (blockIdx.x * blockDim.x + threadIdx.x) >> 5;
    int lane = threadIdx.x & 31;

    const float* feat; const float* rs_s; const int* off; const int* el;
    float* out; int row; bool epi;
    if (w < SVC_N) {
        row = w; feat = svc_feat; rs_s = rs + OFF_A_S; off = offA; el = elA;
        out = aggA; epi = false;
    } else if (w < SVC_N + NODE_N) {
        row = w - SVC_N; feat = inst_feat; rs_s = rs + OFF_B_S; off = offB; el = elB;
        out = aggB; epi = false;
    } else if (w < SVC_N + NODE_N + INST_N) {
        row = w - SVC_N - NODE_N; feat = hC; rs_s = nullptr; off = offC; el = elC;
        out = out_inst; epi = true;
    } else return;

    int b0 = off[row];
    int b1 = off[row + 1];
    float4 acc = make_float4(0.f, 0.f, 0.f, 0.f);

    int e = b0;
    for (; e + 1 < b1; e += 2) {
        int s0 = __ldg(el + e);
        int s1 = __ldg(el + e + 1);
        float4 v0 = __ldg((const float4*)(feat + (size_t)s0 * HID) + lane);
        float4 v1 = __ldg((const float4*)(feat + (size_t)s1 * HID) + lane);
        float r0 = rs_s ? __ldg(rs_s + s0) : 1.f;
        float r1 = rs_s ? __ldg(rs_s + s1) : 1.f;
        acc.x += v0.x * r0; acc.y += v0.y * r0; acc.z += v0.z * r0; acc.w += v0.w * r0;
        acc.x += v1.x * r1; acc.y += v1.y * r1; acc.z += v1.z * r1; acc.w += v1.w * r1;
    }
    if (e < b1) {
        int s0 = __ldg(el + e);
        float4 v0 = __ldg((const float4*)(feat + (size_t)s0 * HID) + lane);
        float r0 = rs_s ? __ldg(rs_s + s0) : 1.f;
        acc.x += v0.x * r0; acc.y += v0.y * r0; acc.z += v0.z * r0; acc.w += v0.w * r0;
    }

    if (epi) {
        float rd = __ldg(rs + OFF_C_D + row);
        float4 bb = __ldg((const float4*)b_node + lane);
        acc.x = acc.x * rd + bb.x;
        acc.y = acc.y * rd + bb.y;
        acc.z = acc.z * rd + bb.z;
        acc.w = acc.w * rd + bb.w;
        acc.x = acc.x >= 0.f ? acc.x : 0.01f * acc.x;
        acc.y = acc.y >= 0.f ? acc.y : 0.01f * acc.y;
        acc.z = acc.z >= 0.f ? acc.z : 0.01f * acc.z;
        acc.w = acc.w >= 0.f ? acc.w : 0.01f * acc.w;
    }
    ((float4*)(out + (size_t)row * HID))[lane] = acc;
}

// ============================================================================
// GEMM core: 32 rows x 128 cols per block, 256 threads, 4x4 register blocking.
// ============================================================================
__device__ __forceinline__ void gemm_tile(
    const float* __restrict__ A, const float* __restrict__ W,
    const float* __restrict__ rs_s, const float* __restrict__ rs_d,
    const float* __restrict__ bias, float* __restrict__ out,
    int n, int base, bool prescale, bool epi, float* sm) {
    float* As = sm;                // [32][128]
    float* Ws = sm + 32 * 128;     // [128][128]
    int tid = threadIdx.x;

    for (int i = tid; i < 128 * 128; i += 256) Ws[i] = W[i];
    for (int i = tid; i < 32 * 128; i += 256) {
        int r = i >> 7, k = i & 127;
        int gr = base + r;
        float v = 0.f;
        if (gr < n) {
            v = A[(size_t)gr * HID + k];
            if (prescale) v *= rs_s[gr];
        }
        As[i] = v;
    }
    __syncthreads();

    int tx = tid & 31;
    int ty = tid >> 5;
    float acc[4][4] = {};

#pragma unroll 8
    for (int k = 0; k < 128; k++) {
        float a0 = As[(ty * 4 + 0) * 128 + k];
        float a1 = As[(ty * 4 + 1) * 128 + k];
        float a2 = As[(ty * 4 + 2) * 128 + k];
        float a3 = As[(ty * 4 + 3) * 128 + k];
        float4 w = *(const float4*)&Ws[k * 128 + tx * 4];
        acc[0][0] += a0 * w.x; acc[0][1] += a0 * w.y; acc[0][2] += a0 * w.z; acc[0][3] += a0 * w.w;
        acc[1][0] += a1 * w.x; acc[1][1] += a1 * w.y; acc[1][2] += a1 * w.z; acc[1][3] += a1 * w.w;
        acc[2][0] += a2 * w.x; acc[2][1] += a2 * w.y; acc[2][2] += a2 * w.z; acc[2][3] += a2 * w.w;
        acc[3][0] += a3 * w.x; acc[3][1] += a3 * w.y; acc[3][2] += a3 * w.z; acc[3][3] += a3 * w.w;
    }

#pragma unroll
    for (int r = 0; r < 4; r++) {
        int gr = base + ty * 4 + r;
        if (gr >= n) continue;
        float4 o;
        if (epi) {
            float rd = rs_d[gr];
            float4 bb = *(const float4*)&bias[tx * 4];
            o.x = acc[r][0] * rd + bb.x;
            o.y = acc[r][1] * rd + bb.y;
            o.z = acc[r][2] * rd + bb.z;
            o.w = acc[r][3] * rd + bb.w;
            o.x = o.x >= 0.f ? o.x : 0.01f * o.x;
            o.y = o.y >= 0.f ? o.y : 0.01f * o.y;
            o.z = o.z >= 0.f ? o.z : 0.01f * o.z;
            o.w = o.w >= 0.f ? o.w : 0.01f * o.w;
        } else {
            o.x = acc[r][0]; o.y = acc[r][1]; o.z = acc[r][2]; o.w = acc[r][3];
        }
        *(float4*)&out[(size_t)gr * HID + tx * 4] = o;
    }
}

// GEMM C: node_feat -> hC with src-norm prescale, no epilogue.
__global__ void __launch_bounds__(256) gemm_c_k(
    const float* __restrict__ A, const float* __restrict__ W,
    const float* __restrict__ rs_s, float* __restrict__ out, int n) {
    extern __shared__ float sm[];
    gemm_tile(A, W, rs_s, nullptr, nullptr, out, n, blockIdx.x * 32, true, false, sm);
}

// Combined GEMM for convs A & B with fused norm+bias+leaky epilogue.
#define NBB 313   // ceil(NODE_N/32)
#define NBA 625   // ceil(SVC_N/32)
__global__ void __launch_bounds__(256) gemm_ab_k(
    const float* __restrict__ aggB, const float* __restrict__ W_inst, const float* __restrict__ b_inst,
    const float* __restrict__ aggA, const float* __restrict__ W_svc, const float* __restrict__ b_svc,
    const float* __restrict__ rs, float* __restrict__ out) {
    extern __shared__ float sm[];
    if (blockIdx.x < NBB) {
        gemm_tile(aggB, W_inst, nullptr, rs + OFF_B_D, b_inst,
                  out, NODE_N, blockIdx.x * 32, false, true, sm);
    } else {
        gemm_tile(aggA, W_svc, nullptr, rs + OFF_A_D, b_svc,
                  out + (size_t)(NODE_N + INST_N) * HID, SVC_N,
                  (blockIdx.x - NBB) * 32, false, true, sm);
    }
}

// ============================================================================
// Host launch
// ============================================================================
extern "C" void kernel_launch(void* const* d_in, const int* in_sizes, int n_in,
                              void* d_out, int out_size) {
    const float* svc_feat  = (const float*)d_in[0];
    const float* inst_feat = (const float*)d_in[1];
    const float* node_feat = (const float*)d_in[2];
    const float* W_svc  = (const float*)d_in[3];
    const float* b_svc  = (const float*)d_in[4];
    const float* W_inst = (const float*)d_in[5];
    const float* b_inst = (const float*)d_in[6];
    const float* W_node = (const float*)d_in[7];
    const float* b_node = (const float*)d_in[8];
    const int* sc_src = (const int*)d_in[9];
    const int* sc_dst = (const int*)d_in[10];
    const int* in_src = (const int*)d_in[11];
    const int* in_dst = (const int*)d_in[12];
    const int* ni_src = (const int*)d_in[13];
    const int* ni_dst = (const int*)d_in[14];
    float* out = (float*)d_out;

    int E_sc = in_sizes[9];
    int E_in = in_sizes[11];
    int E_ni = in_sizes[13];
    int E_tot = E_sc + E_in + E_ni;

    int *cnt, *offA, *offB, *offC, *curA, *curB, *curC, *eA, *eB, *eC, *bsum;
    float *rs, *aggA, *aggB, *hC;
    cudaGetSymbolAddress((void**)&cnt, g_cnt);
    cudaGetSymbolAddress((void**)&rs, g_rs);
    cudaGetSymbolAddress((void**)&offA, g_offA);
    cudaGetSymbolAddress((void**)&offB, g_offB);
    cudaGetSymbolAddress((void**)&offC, g_offC);
    cudaGetSymbolAddress((void**)&curA, g_curA);
    cudaGetSymbolAddress((void**)&curB, g_curB);
    cudaGetSymbolAddress((void**)&curC, g_curC);
    cudaGetSymbolAddress((void**)&eA, g_eA);
    cudaGetSymbolAddress((void**)&eB, g_eB);
    cudaGetSymbolAddress((void**)&eC, g_eC);
    cudaGetSymbolAddress((void**)&bsum, g_bsum);
    cudaGetSymbolAddress((void**)&aggA, g_aggA);
    cudaGetSymbolAddress((void**)&aggB, g_aggB);
    cudaGetSymbolAddress((void**)&hC, g_hC);

    const int SMEM = (32 * 128 + 128 * 128) * 4;  // 80KB
    cudaFuncSetAttribute(gemm_c_k,  cudaFuncAttributeMaxDynamicSharedMemorySize, SMEM);
    cudaFuncSetAttribute(gemm_ab_k, cudaFuncAttributeMaxDynamicSharedMemorySize, SMEM);

    // 1) degrees + norms
    cudaMemsetAsync(cnt, 0, CNT_TOTAL * sizeof(int));
    hist_all_k<<<(E_tot + 255) / 256, 256>>>(sc_src, sc_dst, E_sc,
                                             in_src, in_dst, E_in,
                                             ni_src, ni_dst, E_ni, cnt);
    rsqrt_k<<<(CNT_TOTAL + 255) / 256, 256>>>(cnt, rs, CNT_TOTAL);

    // 2) conv C GEMM (needs only rs) — big kernel early
    gemm_c_k<<<(NODE_N + 31) / 32, 256, SMEM>>>(node_feat, W_node, rs + OFF_C_S, hC, NODE_N);

    // 3) dst-CSR build (fused scans + scatter)
    scan_block_all_k<<<NB_TOTAL, 1024>>>(cnt, offA, offB, offC, bsum);
    scan_bsums_all_k<<<3, 1024>>>(bsum);
    scan_add_all_k<<<NB_TOTAL, 1024>>>(offA, offB, offC, bsum, curA, curB, curC,
                                       E_sc, E_in, E_ni);
    scatter_all_k<<<(E_tot + 255) / 256, 256>>>(sc_src, sc_dst, E_sc,
                                                in_src, in_dst, E_in,
                                                ni_src, ni_dst, E_ni,
                                                curA, curB, curC, eA, eB, eC);

    // 4) all three aggregations in one launch
    int total_warps = SVC_N + NODE_N + INST_N;
    agg_all_k<<<(total_warps * 32 + 255) / 256, 256>>>(
        svc_feat, inst_feat, hC, rs,
        offA, eA, offB, eB, offC, eC,
        b_node, aggA, aggB, out + (size_t)NODE_N * HID);

    // 5) combined A+B GEMM with fused epilogue
    gemm_ab_k<<<NBB + NBA, 256, SMEM>>>(aggB, W_inst, b_inst,
                                        aggA, W_svc, b_svc, rs, out);
}

// round 3
// speedup vs baseline: 1.8158x; 1.4476x over previous
#include <cuda_runtime.h>
#include <cstdint>

#define SVC_N  20000
#define INST_N 100000
#define NODE_N 10000
#define HID    128

#define E_SC_MAX 640000
#define E_IN_MAX 200000
#define E_NI_MAX 200000

// ---- count/rsqrt layout offsets ----
#define OFF_A_S 0
#define OFF_A_D 20000
#define OFF_B_S 40000
#define OFF_B_D 140000
#define OFF_C_S 150000
#define OFF_C_D 160000
#define CNT_TOTAL 260000

#define NB_A 20
#define NB_B 10
#define NB_C 98
#define NB_TOTAL (NB_A + NB_B + NB_C)
#define BS_A 0
#define BS_B 128
#define BS_C 256

// ---- scratch ----
__device__ int   g_cnt[CNT_TOTAL];
__device__ float g_rs[CNT_TOTAL];
__device__ int   g_offA[SVC_N + 1];
__device__ int   g_offB[NODE_N + 1];
__device__ int   g_offC[INST_N + 1];
__device__ int   g_curA[SVC_N];
__device__ int   g_curB[NODE_N];
__device__ int   g_curC[INST_N];
__device__ int   g_eA[E_SC_MAX];
__device__ int   g_eB[E_IN_MAX];
__device__ int   g_eC[E_NI_MAX];
__device__ int   g_bsum[1024];
__device__ float g_aggA[(size_t)SVC_N * HID];
__device__ float g_aggB[(size_t)NODE_N * HID];
__device__ float g_hC[(size_t)NODE_N * HID];

// ============================================================================
// Degree histogram (fused over 3 edge lists)
// ============================================================================
__global__ void hist_all_k(const int* __restrict__ sA, const int* __restrict__ dA, int eA,
                           const int* __restrict__ sB, const int* __restrict__ dB, int eB,
                           const int* __restrict__ sC, const int* __restrict__ dC, int eC,
                           int* __restrict__ cnt) {
    int i = blockIdx.x * blockDim.x + threadIdx.x;
    if (i < eA) {
        atomicAdd(&cnt[OFF_A_S + sA[i]], 1);
        atomicAdd(&cnt[OFF_A_D + dA[i]], 1);
    } else if (i < eA + eB) {
        int j = i - eA;
        atomicAdd(&cnt[OFF_B_S + sB[j]], 1);
        atomicAdd(&cnt[OFF_B_D + dB[j]], 1);
    } else if (i < eA + eB + eC) {
        int j = i - eA - eB;
        atomicAdd(&cnt[OFF_C_S + sC[j]], 1);
        atomicAdd(&cnt[OFF_C_D + dC[j]], 1);
    }
}

__global__ void rsqrt_k(const int* __restrict__ cnt, float* __restrict__ rs, int n) {
    int i = blockIdx.x * blockDim.x + threadIdx.x;
    if (i < n) {
        int c = cnt[i];
        rs[i] = rsqrtf((float)(c > 0 ? c : 1));
    }
}

// ============================================================================
// Fused exclusive scan (3 launches total)
// ============================================================================
__device__ __forceinline__ int block_scan_1024(int* s, int tid, int v) {
    s[tid] = v;
    __syncthreads();
    for (int off = 1; off < 1024; off <<= 1) {
        int t = (tid >= off) ? s[tid - off] : 0;
        __syncthreads();
        s[tid] += t;
        __syncthreads();
    }
    return s[tid];
}

__global__ void scan_block_all_k(const int* __restrict__ cnt,
                                 int* __restrict__ offA, int* __restrict__ offB,
                                 int* __restrict__ offC, int* __restrict__ bs) {
    __shared__ int s[1024];
    int bid = blockIdx.x, tid = threadIdx.x;
    const int* in; int n; int* out; int* bsum; int chunk;
    if (bid < NB_A)              { in = cnt + OFF_A_D; n = SVC_N;  out = offA; bsum = bs + BS_A; chunk = bid; }
    else if (bid < NB_A + NB_B)  { in = cnt + OFF_B_D; n = NODE_N; out = offB; bsum = bs + BS_B; chunk = bid - NB_A; }
    else                         { in = cnt + OFF_C_D; n = INST_N; out = offC; bsum = bs + BS_C; chunk = bid - NB_A - NB_B; }
    int gid = chunk * 1024 + tid;
    int v = (gid < n) ? in[gid] : 0;
    int inc = block_scan_1024(s, tid, v);
    if (gid < n) out[gid] = inc - v;
    if (tid == 1023) bsum[chunk] = inc;
}

__global__ void scan_bsums_all_k(int* __restrict__ bs) {
    __shared__ int s[1024];
    int tid = threadIdx.x;
    int* seg; int nb;
    if (blockIdx.x == 0)      { seg = bs + BS_A; nb = NB_A; }
    else if (blockIdx.x == 1) { seg = bs + BS_B; nb = NB_B; }
    else                      { seg = bs + BS_C; nb = NB_C; }
    int v = (tid < nb) ? seg[tid] : 0;
    int inc = block_scan_1024(s, tid, v);
    if (tid < nb) seg[tid] = inc - v;
}

__global__ void scan_add_all_k(int* __restrict__ offA, int* __restrict__ offB,
                               int* __restrict__ offC, const int* __restrict__ bs,
                               int* __restrict__ curA, int* __restrict__ curB,
                               int* __restrict__ curC,
                               int eA, int eB, int eC) {
    int bid = blockIdx.x, tid = threadIdx.x;
    int* out; const int* bsum; int n, E, chunk; int* cur;
    if (bid < NB_A)              { out = offA; bsum = bs + BS_A; n = SVC_N;  E = eA; chunk = bid;               cur = curA; }
    else if (bid < NB_A + NB_B)  { out = offB; bsum = bs + BS_B; n = NODE_N; E = eB; chunk = bid - NB_A;        cur = curB; }
    else                         { out = offC; bsum = bs + BS_C; n = INST_N; E = eC; chunk = bid - NB_A - NB_B; cur = curC; }
    int gid = chunk * 1024 + tid;
    if (gid < n) {
        int o = out[gid] + bsum[chunk];
        out[gid] = o;
        cur[gid] = o;
    }
    if (chunk == 0 && tid == 0) out[n] = E;
}

// ============================================================================
// Fused scatter into dst-CSR
// ============================================================================
__global__ void scatter_all_k(const int* __restrict__ sA, const int* __restrict__ dA, int eA,
                              const int* __restrict__ sB, const int* __restrict__ dB, int eB,
                              const int* __restrict__ sC, const int* __restrict__ dC, int eC,
                              int* __restrict__ curA, int* __restrict__ curB, int* __restrict__ curC,
                              int* __restrict__ elA, int* __restrict__ elB, int* __restrict__ elC) {
    int i = blockIdx.x * blockDim.x + threadIdx.x;
    if (i < eA) {
        int p = atomicAdd(&curA[dA[i]], 1);
        elA[p] = sA[i];
    } else if (i < eA + eB) {
        int j = i - eA;
        int p = atomicAdd(&curB[dB[j]], 1);
        elB[p] = sB[j];
    } else if (i < eA + eB + eC) {
        int j = i - eA - eB;
        int p = atomicAdd(&curC[dC[j]], 1);
        elC[p] = sC[j];
    }
}

// ============================================================================
// Combined aggregation: one warp per dst row across ALL three convs.
// ============================================================================
__global__ void __launch_bounds__(256) agg_all_k(
    const float* __restrict__ svc_feat, const float* __restrict__ inst_feat,
    const float* __restrict__ hC, const float* __restrict__ rs,
    const int* __restrict__ offA, const int* __restrict__ elA,
    const int* __restrict__ offB, const int* __restrict__ elB,
    const int* __restrict__ offC, const int* __restrict__ elC,
    const float* __restrict__ b_node, float* __restrict__ aggA,
    float* __restrict__ aggB, float* __restrict__ out_inst) {
    int w = (blockIdx.x * blockDim.x + threadIdx.x) >> 5;
    int lane = threadIdx.x & 31;

    const float* feat; const float* rs_s; const int* off; const int* el;
    float* out; int row; bool epi;
    if (w < SVC_N) {
        row = w; feat = svc_feat; rs_s = rs + OFF_A_S; off = offA; el = elA;
        out = aggA; epi = false;
    } else if (w < SVC_N + NODE_N) {
        row = w - SVC_N; feat = inst_feat; rs_s = rs + OFF_B_S; off = offB; el = elB;
        out = aggB; epi = false;
    } else if (w < SVC_N + NODE_N + INST_N) {
        row = w - SVC_N - NODE_N; feat = hC; rs_s = nullptr; off = offC; el = elC;
        out = out_inst; epi = true;
    } else return;

    int b0 = off[row];
    int b1 = off[row + 1];
    float4 acc = make_float4(0.f, 0.f, 0.f, 0.f);

    int e = b0;
    for (; e + 3 < b1; e += 4) {
        int s0 = __ldg(el + e);
        int s1 = __ldg(el + e + 1);
        int s2 = __ldg(el + e + 2);
        int s3 = __ldg(el + e + 3);
        float4 v0 = __ldg((const float4*)(feat + (size_t)s0 * HID) + lane);
        float4 v1 = __ldg((const float4*)(feat + (size_t)s1 * HID) + lane);
        float4 v2 = __ldg((const float4*)(feat + (size_t)s2 * HID) + lane);
        float4 v3 = __ldg((const float4*)(feat + (size_t)s3 * HID) + lane);
        float r0 = rs_s ? __ldg(rs_s + s0) : 1.f;
        float r1 = rs_s ? __ldg(rs_s + s1) : 1.f;
        float r2 = rs_s ? __ldg(rs_s + s2) : 1.f;
        float r3 = rs_s ? __ldg(rs_s + s3) : 1.f;
        acc.x += v0.x * r0; acc.y += v0.y * r0; acc.z += v0.z * r0; acc.w += v0.w * r0;
        acc.x += v1.x * r1; acc.y += v1.y * r1; acc.z += v1.z * r1; acc.w += v1.w * r1;
        acc.x += v2.x * r2; acc.y += v2.y * r2; acc.z += v2.z * r2; acc.w += v2.w * r2;
        acc.x += v3.x * r3; acc.y += v3.y * r3; acc.z += v3.z * r3; acc.w += v3.w * r3;
    }
    for (; e < b1; e++) {
        int s0 = __ldg(el + e);
        float4 v0 = __ldg((const float4*)(feat + (size_t)s0 * HID) + lane);
        float r0 = rs_s ? __ldg(rs_s + s0) : 1.f;
        acc.x += v0.x * r0; acc.y += v0.y * r0; acc.z += v0.z * r0; acc.w += v0.w * r0;
    }

    if (epi) {
        float rd = __ldg(rs + OFF_C_D + row);
        float4 bb = __ldg((const float4*)b_node + lane);
        acc.x = acc.x * rd + bb.x;
        acc.y = acc.y * rd + bb.y;
        acc.z = acc.z * rd + bb.z;
        acc.w = acc.w * rd + bb.w;
        acc.x = acc.x >= 0.f ? acc.x : 0.01f * acc.x;
        acc.y = acc.y >= 0.f ? acc.y : 0.01f * acc.y;
        acc.z = acc.z >= 0.f ? acc.z : 0.01f * acc.z;
        acc.w = acc.w >= 0.f ? acc.w : 0.01f * acc.w;
    }
    ((float4*)(out + (size_t)row * HID))[lane] = acc;
}

// ============================================================================
// TF32 tensor-core GEMM: out[n,128] = A[n,128] @ W[128,128]
// Block: 64 rows x 128 cols, 256 threads (8 warps, 4 row x 2 col).
// Warp tile: 16 rows x 64 cols = 8 mma n-tiles of m16n8k8.
// smem: As[64][132] + Ws[128][132] (tf32-rounded), padded for bank spread.
// ============================================================================
#define AS_LD 132
#define SMEM_GEMM ((64 * AS_LD + 128 * AS_LD) * 4)

__device__ __forceinline__ float tf32_round(float v) {
    uint32_t r;
    asm("cvt.rna.tf32.f32 %0, %1;" : "=r"(r) : "f"(v));
    return __uint_as_float(r);
}

__device__ __forceinline__ void mma_tf32(float4& d, uint32_t a0, uint32_t a1,
                                         uint32_t a2, uint32_t a3,
                                         uint32_t b0, uint32_t b1) {
    asm volatile(
        "mma.sync.aligned.m16n8k8.row.col.f32.tf32.tf32.f32 "
        "{%0,%1,%2,%3}, {%4,%5,%6,%7}, {%8,%9}, {%0,%1,%2,%3};"
        : "+f"(d.x), "+f"(d.y), "+f"(d.z), "+f"(d.w)
        : "r"(a0), "r"(a1), "r"(a2), "r"(a3), "r"(b0), "r"(b1));
}

__device__ __forceinline__ void gemm_tile_tf32(
    const float* __restrict__ A, const float* __restrict__ W,
    const float* __restrict__ rs_s, const float* __restrict__ rs_d,
    const float* __restrict__ bias, float* __restrict__ out,
    int n, int base, bool prescale, bool epi, float* sm) {
    float* As = sm;                 // [64][AS_LD]
    float* Ws = sm + 64 * AS_LD;    // [128][AS_LD]
    int tid = threadIdx.x;

    // Stage W (tf32-rounded)
    for (int i = tid; i < 128 * 32; i += 256) {       // 128x128 / 4
        int k = i >> 5, ncol4 = (i & 31) * 4;
        float4 w = __ldg((const float4*)(W + k * HID + ncol4));
        w.x = tf32_round(w.x); w.y = tf32_round(w.y);
        w.z = tf32_round(w.z); w.w = tf32_round(w.w);
        *(float4*)&Ws[k * AS_LD + ncol4] = w;
    }
    // Stage A rows (prescaled, tf32-rounded, zero-padded)
    for (int i = tid; i < 64 * 32; i += 256) {        // 64x128 / 4
        int r = i >> 5, k4 = (i & 31) * 4;
        int gr = base + r;
        float4 v = make_float4(0.f, 0.f, 0.f, 0.f);
        if (gr < n) {
            v = __ldg((const float4*)(A + (size_t)gr * HID + k4));
            if (prescale) {
                float rv = __ldg(rs_s + gr);
                v.x *= rv; v.y *= rv; v.z *= rv; v.w *= rv;
            }
        }
        v.x = tf32_round(v.x); v.y = tf32_round(v.y);
        v.z = tf32_round(v.z); v.w = tf32_round(v.w);
        *(float4*)&As[r * AS_LD + k4] = v;
    }
    __syncthreads();

    int warp = tid >> 5, lane = tid & 31;
    int wr = warp >> 1;         // 0..3 row warp
    int wc = warp & 1;          // 0..1 col warp
    int g = lane >> 2;          // group 0..7
    int tig = lane & 3;         // thread in group

    float4 acc[8];
#pragma unroll
    for (int t = 0; t < 8; t++) acc[t] = make_float4(0.f, 0.f, 0.f, 0.f);

    int arow0 = (wr * 16 + g) * AS_LD;
    int arow1 = (wr * 16 + g + 8) * AS_LD;
    int bcol = wc * 64 + g;

#pragma unroll
    for (int k0 = 0; k0 < 128; k0 += 8) {
        uint32_t a0 = __float_as_uint(As[arow0 + k0 + tig]);
        uint32_t a1 = __float_as_uint(As[arow1 + k0 + tig]);
        uint32_t a2 = __float_as_uint(As[arow0 + k0 + tig + 4]);
        uint32_t a3 = __float_as_uint(As[arow1 + k0 + tig + 4]);
        int wk0 = (k0 + tig) * AS_LD;
        int wk1 = (k0 + tig + 4) * AS_LD;
#pragma unroll
        for (int t = 0; t < 8; t++) {
            uint32_t b0 = __float_as_uint(Ws[wk0 + bcol + t * 8]);
            uint32_t b1 = __float_as_uint(Ws[wk1 + bcol + t * 8]);
            mma_tf32(acc[t], a0, a1, a2, a3, b0, b1);
        }
    }

    // Epilogue: c0 (row g, col 2*tig), c1 (+1), c2 (row g+8), c3 (+1)
    int row0 = base + wr * 16 + g;
    int row1 = row0 + 8;
    float rd0 = 1.f, rd1 = 1.f;
    if (epi) {
        if (row0 < n) rd0 = __ldg(rs_d + row0);
        if (row1 < n) rd1 = __ldg(rs_d + row1);
    }
#pragma unroll
    for (int t = 0; t < 8; t++) {
        int col = wc * 64 + t * 8 + tig * 2;
        float2 lo = make_float2(acc[t].x, acc[t].y);
        float2 hi = make_float2(acc[t].z, acc[t].w);
        if (epi) {
            float bx = __ldg(bias + col), by = __ldg(bias + col + 1);
            lo.x = lo.x * rd0 + bx; lo.y = lo.y * rd0 + by;
            hi.x = hi.x * rd1 + bx; hi.y = hi.y * rd1 + by;
            lo.x = lo.x >= 0.f ? lo.x : 0.01f * lo.x;
            lo.y = lo.y >= 0.f ? lo.y : 0.01f * lo.y;
            hi.x = hi.x >= 0.f ? hi.x : 0.01f * hi.x;
            hi.y = hi.y >= 0.f ? hi.y : 0.01f * hi.y;
        }
        if (row0 < n) *(float2*)&out[(size_t)row0 * HID + col] = lo;
        if (row1 < n) *(float2*)&out[(size_t)row1 * HID + col] = hi;
    }
}

// GEMM C: node_feat -> hC with src-norm prescale, no epilogue.
__global__ void __launch_bounds__(256) gemm_c_k(
    const float* __restrict__ A, const float* __restrict__ W,
    const float* __restrict__ rs_s, float* __restrict__ out, int n) {
    extern __shared__ float sm[];
    gemm_tile_tf32(A, W, rs_s, nullptr, nullptr, out, n, blockIdx.x * 64, true, false, sm);
}

// Combined GEMM for convs A & B with fused norm+bias+leaky epilogue.
#define NBB64 157   // ceil(NODE_N/64)
#define NBA64 313   // ceil(SVC_N/64)
__global__ void __launch_bounds__(256) gemm_ab_k(
    const float* __restrict__ aggB, const float* __restrict__ W_inst, const float* __restrict__ b_inst,
    const float* __restrict__ aggA, const float* __restrict__ W_svc, const float* __restrict__ b_svc,
    const float* __restrict__ rs, float* __restrict__ out) {
    extern __shared__ float sm[];
    if (blockIdx.x < NBB64) {
        gemm_tile_tf32(aggB, W_inst, nullptr, rs + OFF_B_D, b_inst,
                       out, NODE_N, blockIdx.x * 64, false, true, sm);
    } else {
        gemm_tile_tf32(aggA, W_svc, nullptr, rs + OFF_A_D, b_svc,
                       out + (size_t)(NODE_N + INST_N) * HID, SVC_N,
                       (blockIdx.x - NBB64) * 64, false, true, sm);
    }
}

// ============================================================================
// Host launch
// ============================================================================
extern "C" void kernel_launch(void* const* d_in, const int* in_sizes, int n_in,
                              void* d_out, int out_size) {
    const float* svc_feat  = (const float*)d_in[0];
    const float* inst_feat = (const float*)d_in[1];
    const float* node_feat = (const float*)d_in[2];
    const float* W_svc  = (const float*)d_in[3];
    const float* b_svc  = (const float*)d_in[4];
    const float* W_inst = (const float*)d_in[5];
    const float* b_inst = (const float*)d_in[6];
    const float* W_node = (const float*)d_in[7];
    const float* b_node = (const float*)d_in[8];
    const int* sc_src = (const int*)d_in[9];
    const int* sc_dst = (const int*)d_in[10];
    const int* in_src = (const int*)d_in[11];
    const int* in_dst = (const int*)d_in[12];
    const int* ni_src = (const int*)d_in[13];
    const int* ni_dst = (const int*)d_in[14];
    float* out = (float*)d_out;

    int E_sc = in_sizes[9];
    int E_in = in_sizes[11];
    int E_ni = in_sizes[13];
    int E_tot = E_sc + E_in + E_ni;

    int *cnt, *offA, *offB, *offC, *curA, *curB, *curC, *eA, *eB, *eC, *bsum;
    float *rs, *aggA, *aggB, *hC;
    cudaGetSymbolAddress((void**)&cnt, g_cnt);
    cudaGetSymbolAddress((void**)&rs, g_rs);
    cudaGetSymbolAddress((void**)&offA, g_offA);
    cudaGetSymbolAddress((void**)&offB, g_offB);
    cudaGetSymbolAddress((void**)&offC, g_offC);
    cudaGetSymbolAddress((void**)&curA, g_curA);
    cudaGetSymbolAddress((void**)&curB, g_curB);
    cudaGetSymbolAddress((void**)&curC, g_curC);
    cudaGetSymbolAddress((void**)&eA, g_eA);
    cudaGetSymbolAddress((void**)&eB, g_eB);
    cudaGetSymbolAddress((void**)&eC, g_eC);
    cudaGetSymbolAddress((void**)&bsum, g_bsum);
    cudaGetSymbolAddress((void**)&aggA, g_aggA);
    cudaGetSymbolAddress((void**)&aggB, g_aggB);
    cudaGetSymbolAddress((void**)&hC, g_hC);

    cudaFuncSetAttribute(gemm_c_k,  cudaFuncAttributeMaxDynamicSharedMemorySize, SMEM_GEMM);
    cudaFuncSetAttribute(gemm_ab_k, cudaFuncAttributeMaxDynamicSharedMemorySize, SMEM_GEMM);

    // 1) degrees + norms
    cudaMemsetAsync(cnt, 0, CNT_TOTAL * sizeof(int));
    hist_all_k<<<(E_tot + 255) / 256, 256>>>(sc_src, sc_dst, E_sc,
                                             in_src, in_dst, E_in,
                                             ni_src, ni_dst, E_ni, cnt);
    rsqrt_k<<<(CNT_TOTAL + 255) / 256, 256>>>(cnt, rs, CNT_TOTAL);

    // 2) conv C GEMM (needs only rs)
    gemm_c_k<<<(NODE_N + 63) / 64, 256, SMEM_GEMM>>>(node_feat, W_node, rs + OFF_C_S, hC, NODE_N);

    // 3) dst-CSR build
    scan_block_all_k<<<NB_TOTAL, 1024>>>(cnt, offA, offB, offC, bsum);
    scan_bsums_all_k<<<3, 1024>>>(bsum);
    scan_add_all_k<<<NB_TOTAL, 1024>>>(offA, offB, offC, bsum, curA, curB, curC,
                                       E_sc, E_in, E_ni);
    scatter_all_k<<<(E_tot + 255) / 256, 256>>>(sc_src, sc_dst, E_sc,
                                                in_src, in_dst, E_in,
                                                ni_src, ni_dst, E_ni,
                                                curA, curB, curC, eA, eB, eC);

    // 4) all three aggregations in one launch
    int total_warps = SVC_N + NODE_N + INST_N;
    agg_all_k<<<(total_warps * 32 + 255) / 256, 256>>>(
        svc_feat, inst_feat, hC, rs,
        offA, eA, offB, eB, offC, eC,
        b_node, aggA, aggB, out + (size_t)NODE_N * HID);

    // 5) combined A+B GEMM with fused epilogue
    gemm_ab_k<<<NBB64 + NBA64, 256, SMEM_GEMM>>>(aggB, W_inst, b_inst,
                                                 aggA, W_svc, b_svc, rs, out);
}

// round 4
// speedup vs baseline: 1.8904x; 1.0411x over previous
#include <cuda_runtime.h>
#include <cstdint>

#define SVC_N  20000
#define INST_N 100000
#define NODE_N 10000
#define HID    128

#define E_SC_MAX 640000
#define E_IN_MAX 200000
#define E_NI_MAX 200000

// ---- count/rsqrt layout offsets ----
#define OFF_A_S 0
#define OFF_A_D 20000
#define OFF_B_S 40000
#define OFF_B_D 140000
#define OFF_C_S 150000
#define OFF_C_D 160000
#define CNT_TOTAL 260000

#define NB_A 20
#define NB_B 10
#define NB_C 98
#define NB_TOTAL (NB_A + NB_B + NB_C)   // 128 scan blocks
#define NB_SRC 127                       // pure-rsqrt blocks (130048 >= 130000 src entries)

// ---- scratch ----
__device__ int   g_cnt[CNT_TOTAL];       // zero at load; re-zeroed by scatter each run
__device__ float g_rs[CNT_TOTAL];
__device__ int   g_offA[SVC_N + 1];
__device__ int   g_offB[NODE_N + 1];
__device__ int   g_offC[INST_N + 1];
__device__ int   g_curA[SVC_N];
__device__ int   g_curB[NODE_N];
__device__ int   g_curC[INST_N];
__device__ int   g_eA[E_SC_MAX];
__device__ int   g_eB[E_IN_MAX];
__device__ int   g_eC[E_NI_MAX];
__device__ int   g_bsum[384];
__device__ int   g_bflag[384];           // zeroed by hist each run
__device__ float g_aggA[(size_t)SVC_N * HID];
__device__ float g_aggB[(size_t)NODE_N * HID];
__device__ float g_hC[(size_t)NODE_N * HID];

// ============================================================================
// Degree histogram (fused over 3 edge lists) + lookback-flag reset
// ============================================================================
__global__ void hist_all_k(const int* __restrict__ sA, const int* __restrict__ dA, int eA,
                           const int* __restrict__ sB, const int* __restrict__ dB, int eB,
                           const int* __restrict__ sC, const int* __restrict__ dC, int eC,
                           int* __restrict__ cnt) {
    int i = blockIdx.x * blockDim.x + threadIdx.x;
    if (i < 384) g_bflag[i] = 0;
    if (i < eA) {
        atomicAdd(&cnt[OFF_A_S + sA[i]], 1);
        atomicAdd(&cnt[OFF_A_D + dA[i]], 1);
    } else if (i < eA + eB) {
        int j = i - eA;
        atomicAdd(&cnt[OFF_B_S + sB[j]], 1);
        atomicAdd(&cnt[OFF_B_D + dB[j]], 1);
    } else if (i < eA + eB + eC) {
        int j = i - eA - eB;
        atomicAdd(&cnt[OFF_C_S + sC[j]], 1);
        atomicAdd(&cnt[OFF_C_D + dC[j]], 1);
    }
}

// ============================================================================
// Fused single-kernel: exclusive scans of the 3 dst-degree arrays (aggregate
// lookback across blocks) + rsqrt norms for ALL cnt entries.
// Blocks [0,128): scan + dst rsqrt. Blocks [128,255): src rsqrt only.
// All 255 blocks fit in one wave (2 x 1024-thread blocks per SM, 148 SMs).
// ============================================================================
__global__ void __launch_bounds__(1024) scanrs_k(
    const int* __restrict__ cnt, float* __restrict__ rs,
    int* __restrict__ offA, int* __restrict__ offB, int* __restrict__ offC,
    int* __restrict__ curA, int* __restrict__ curB, int* __restrict__ curC,
    int eAn, int eBn, int eCn) {
    int bid = blockIdx.x, tid = threadIdx.x;

    if (bid >= NB_TOTAL) {
        // pure rsqrt over src ranges (130000 entries, non-contiguous layout)
        int j = (bid - NB_TOTAL) * 1024 + tid;
        int idx;
        if (j < 20000)       idx = OFF_A_S + j;
        else if (j < 120000) idx = OFF_B_S + (j - 20000);
        else if (j < 130000) idx = OFF_C_S + (j - 120000);
        else return;
        int c = cnt[idx];
        rs[idx] = rsqrtf((float)(c > 0 ? c : 1));
        return;
    }

    int seg, chunk, n, E, cntoff;
    int *off, *cur;
    if (bid < NB_A)              { seg = 0; chunk = bid;               n = SVC_N;  E = eAn; cntoff = OFF_A_D; off = offA; cur = curA; }
    else if (bid < NB_A + NB_B)  { seg = 1; chunk = bid - NB_A;        n = NODE_N; E = eBn; cntoff = OFF_B_D; off = offB; cur = curB; }
    else                         { seg = 2; chunk = bid - NB_A - NB_B; n = INST_N; E = eCn; cntoff = OFF_C_D; off = offC; cur = curC; }

    int gid = chunk * 1024 + tid;
    int v = (gid < n) ? cnt[cntoff + gid] : 0;
    if (gid < n) rs[cntoff + gid] = rsqrtf((float)(v > 0 ? v : 1));

    // --- shuffle block scan (inclusive) ---
    int lane = tid & 31, w = tid >> 5;
    int x = v;
#pragma unroll
    for (int o = 1; o < 32; o <<= 1) {
        int y = __shfl_up_sync(0xffffffffu, x, o);
        if (lane >= o) x += y;
    }
    __shared__ int wsum[32];
    if (lane == 31) wsum[w] = x;
    __syncthreads();
    if (w == 0) {
        int t = wsum[lane];
#pragma unroll
        for (int o = 1; o < 32; o <<= 1) {
            int y = __shfl_up_sync(0xffffffffu, t, o);
            if (lane >= o) t += y;
        }
        wsum[lane] = t;
    }
    __syncthreads();
    int incl  = x + (w > 0 ? wsum[w - 1] : 0);
    int total = wsum[31];

    // --- publish block aggregate ---
    int segbase = seg * 128;
    if (tid == 0) {
        g_bsum[segbase + chunk] = total;
        __threadfence();
        atomicExch(&g_bflag[segbase + chunk], 1);
    }

    // --- lookback: parallel sum of predecessor aggregates (chunk <= 97) ---
    int p = 0;
    if (tid < chunk) {
        while (atomicAdd(&g_bflag[segbase + tid], 0) == 0) {}
        p = __ldcg(&g_bsum[segbase + tid]);
    }
    if (tid < 128) {
#pragma unroll
        for (int o = 16; o > 0; o >>= 1) p += __shfl_down_sync(0xffffffffu, p, o);
    }
    __shared__ int warp_p[4];
    __shared__ int s_pre;
    if (tid < 128 && lane == 0) warp_p[w] = p;
    __syncthreads();
    if (tid == 0) s_pre = warp_p[0] + warp_p[1] + warp_p[2] + warp_p[3];
    __syncthreads();
    int prefix = s_pre;

    if (gid < n) {
        int o = prefix + incl - v;
        off[gid] = o;
        cur[gid] = o;
    }
    if (chunk == 0 && tid == 0) off[n] = E;
}

// ============================================================================
// Fused scatter into dst-CSR + re-zero cnt for the next graph replay
// ============================================================================
__global__ void scatter_all_k(const int* __restrict__ sA, const int* __restrict__ dA, int eA,
                              const int* __restrict__ sB, const int* __restrict__ dB, int eB,
                              const int* __restrict__ sC, const int* __restrict__ dC, int eC,
                              int* __restrict__ curA, int* __restrict__ curB, int* __restrict__ curC,
                              int* __restrict__ elA, int* __restrict__ elB, int* __restrict__ elC,
                              int* __restrict__ cnt) {
    int i = blockIdx.x * blockDim.x + threadIdx.x;
    if (i < CNT_TOTAL) cnt[i] = 0;   // cnt fully consumed by scanrs_k (prior launch)
    if (i < eA) {
        int p = atomicAdd(&curA[dA[i]], 1);
        elA[p] = sA[i];
    } else if (i < eA + eB) {
        int j = i - eA;
        int p = atomicAdd(&curB[dB[j]], 1);
        elB[p] = sB[j];
    } else if (i < eA + eB + eC) {
        int j = i - eA - eB;
        int p = atomicAdd(&curC[dC[j]], 1);
        elC[p] = sC[j];
    }
}

// ============================================================================
// Combined aggregation: one warp per dst row across ALL three convs.
// ============================================================================
__global__ void __launch_bounds__(256) agg_all_k(
    const float* __restrict__ svc_feat, const float* __restrict__ inst_feat,
    const float* __restrict__ hC, const float* __restrict__ rs,
    const int* __restrict__ offA, const int* __restrict__ elA,
    const int* __restrict__ offB, const int* __restrict__ elB,
    const int* __restrict__ offC, const int* __restrict__ elC,
    const float* __restrict__ b_node, float* __restrict__ aggA,
    float* __restrict__ aggB, float* __restrict__ out_inst) {
    int w = (blockIdx.x * blockDim.x + threadIdx.x) >> 5;
    int lane = threadIdx.x & 31;

    const float* feat; const float* rs_s; const int* off; const int* el;
    float* out; int row; bool epi;
    if (w < SVC_N) {
        row = w; feat = svc_feat; rs_s = rs + OFF_A_S; off = offA; el = elA;
        out = aggA; epi = false;
    } else if (w < SVC_N + NODE_N) {
        row = w - SVC_N; feat = inst_feat; rs_s = rs + OFF_B_S; off = offB; el = elB;
        out = aggB; epi = false;
    } else if (w < SVC_N + NODE_N + INST_N) {
        row = w - SVC_N - NODE_N; feat = hC; rs_s = nullptr; off = offC; el = elC;
        out = out_inst; epi = true;
    } else return;

    int b0 = off[row];
    int b1 = off[row + 1];
    float4 acc = make_float4(0.f, 0.f, 0.f, 0.f);

    int e = b0;
    for (; e + 3 < b1; e += 4) {
        int s0 = __ldg(el + e);
        int s1 = __ldg(el + e + 1);
        int s2 = __ldg(el + e + 2);
        int s3 = __ldg(el + e + 3);
        float4 v0 = __ldg((const float4*)(feat + (size_t)s0 * HID) + lane);
        float4 v1 = __ldg((const float4*)(feat + (size_t)s1 * HID) + lane);
        float4 v2 = __ldg((const float4*)(feat + (size_t)s2 * HID) + lane);
        float4 v3 = __ldg((const float4*)(feat + (size_t)s3 * HID) + lane);
        float r0 = rs_s ? __ldg(rs_s + s0) : 1.f;
        float r1 = rs_s ? __ldg(rs_s + s1) : 1.f;
        float r2 = rs_s ? __ldg(rs_s + s2) : 1.f;
        float r3 = rs_s ? __ldg(rs_s + s3) : 1.f;
        acc.x += v0.x * r0; acc.y += v0.y * r0; acc.z += v0.z * r0; acc.w += v0.w * r0;
        acc.x += v1.x * r1; acc.y += v1.y * r1; acc.z += v1.z * r1; acc.w += v1.w * r1;
        acc.x += v2.x * r2; acc.y += v2.y * r2; acc.z += v2.z * r2; acc.w += v2.w * r2;
        acc.x += v3.x * r3; acc.y += v3.y * r3; acc.z += v3.z * r3; acc.w += v3.w * r3;
    }
    for (; e < b1; e++) {
        int s0 = __ldg(el + e);
        float4 v0 = __ldg((const float4*)(feat + (size_t)s0 * HID) + lane);
        float r0 = rs_s ? __ldg(rs_s + s0) : 1.f;
        acc.x += v0.x * r0; acc.y += v0.y * r0; acc.z += v0.z * r0; acc.w += v0.w * r0;
    }

    if (epi) {
        float rd = __ldg(rs + OFF_C_D + row);
        float4 bb = __ldg((const float4*)b_node + lane);
        acc.x = acc.x * rd + bb.x;
        acc.y = acc.y * rd + bb.y;
        acc.z = acc.z * rd + bb.z;
        acc.w = acc.w * rd + bb.w;
        acc.x = acc.x >= 0.f ? acc.x : 0.01f * acc.x;
        acc.y = acc.y >= 0.f ? acc.y : 0.01f * acc.y;
        acc.z = acc.z >= 0.f ? acc.z : 0.01f * acc.z;
        acc.w = acc.w >= 0.f ? acc.w : 0.01f * acc.w;
    }
    ((float4*)(out + (size_t)row * HID))[lane] = acc;
}

// ============================================================================
// TF32 tensor-core GEMM: out[n,128] = A[n,128] @ W[128,128]
// Block: 64 rows x 128 cols, 256 threads (8 warps, 4 row x 2 col).
// ============================================================================
#define AS_LD 132
#define SMEM_GEMM ((64 * AS_LD + 128 * AS_LD) * 4)

__device__ __forceinline__ float tf32_round(float v) {
    uint32_t r;
    asm("cvt.rna.tf32.f32 %0, %1;" : "=r"(r) : "f"(v));
    return __uint_as_float(r);
}

__device__ __forceinline__ void mma_tf32(float4& d, uint32_t a0, uint32_t a1,
                                         uint32_t a2, uint32_t a3,
                                         uint32_t b0, uint32_t b1) {
    asm volatile(
        "mma.sync.aligned.m16n8k8.row.col.f32.tf32.tf32.f32 "
        "{%0,%1,%2,%3}, {%4,%5,%6,%7}, {%8,%9}, {%0,%1,%2,%3};"
        : "+f"(d.x), "+f"(d.y), "+f"(d.z), "+f"(d.w)
        : "r"(a0), "r"(a1), "r"(a2), "r"(a3), "r"(b0), "r"(b1));
}

__device__ __forceinline__ void gemm_tile_tf32(
    const float* __restrict__ A, const float* __restrict__ W,
    const float* __restrict__ rs_s, const float* __restrict__ rs_d,
    const float* __restrict__ bias, float* __restrict__ out,
    int n, int base, bool prescale, bool epi, float* sm) {
    float* As = sm;                 // [64][AS_LD]
    float* Ws = sm + 64 * AS_LD;    // [128][AS_LD]
    int tid = threadIdx.x;

    for (int i = tid; i < 128 * 32; i += 256) {
        int k = i >> 5, ncol4 = (i & 31) * 4;
        float4 w = __ldg((const float4*)(W + k * HID + ncol4));
        w.x = tf32_round(w.x); w.y = tf32_round(w.y);
        w.z = tf32_round(w.z); w.w = tf32_round(w.w);
        *(float4*)&Ws[k * AS_LD + ncol4] = w;
    }
    for (int i = tid; i < 64 * 32; i += 256) {
        int r = i >> 5, k4 = (i & 31) * 4;
        int gr = base + r;
        float4 v = make_float4(0.f, 0.f, 0.f, 0.f);
        if (gr < n) {
            v = __ldg((const float4*)(A + (size_t)gr * HID + k4));
            if (prescale) {
                float rv = __ldg(rs_s + gr);
                v.x *= rv; v.y *= rv; v.z *= rv; v.w *= rv;
            }
        }
        v.x = tf32_round(v.x); v.y = tf32_round(v.y);
        v.z = tf32_round(v.z); v.w = tf32_round(v.w);
        *(float4*)&As[r * AS_LD + k4] = v;
    }
    __syncthreads();

    int warp = tid >> 5, lane = tid & 31;
    int wr = warp >> 1;
    int wc = warp & 1;
    int g = lane >> 2;
    int tig = lane & 3;

    float4 acc[8];
#pragma unroll
    for (int t = 0; t < 8; t++) acc[t] = make_float4(0.f, 0.f, 0.f, 0.f);

    int arow0 = (wr * 16 + g) * AS_LD;
    int arow1 = (wr * 16 + g + 8) * AS_LD;
    int bcol = wc * 64 + g;

#pragma unroll
    for (int k0 = 0; k0 < 128; k0 += 8) {
        uint32_t a0 = __float_as_uint(As[arow0 + k0 + tig]);
        uint32_t a1 = __float_as_uint(As[arow1 + k0 + tig]);
        uint32_t a2 = __float_as_uint(As[arow0 + k0 + tig + 4]);
        uint32_t a3 = __float_as_uint(As[arow1 + k0 + tig + 4]);
        int wk0 = (k0 + tig) * AS_LD;
        int wk1 = (k0 + tig + 4) * AS_LD;
#pragma unroll
        for (int t = 0; t < 8; t++) {
            uint32_t b0 = __float_as_uint(Ws[wk0 + bcol + t * 8]);
            uint32_t b1 = __float_as_uint(Ws[wk1 + bcol + t * 8]);
            mma_tf32(acc[t], a0, a1, a2, a3, b0, b1);
        }
    }

    int row0 = base + wr * 16 + g;
    int row1 = row0 + 8;
    float rd0 = 1.f, rd1 = 1.f;
    if (epi) {
        if (row0 < n) rd0 = __ldg(rs_d + row0);
        if (row1 < n) rd1 = __ldg(rs_d + row1);
    }
#pragma unroll
    for (int t = 0; t < 8; t++) {
        int col = wc * 64 + t * 8 + tig * 2;
        float2 lo = make_float2(acc[t].x, acc[t].y);
        float2 hi = make_float2(acc[t].z, acc[t].w);
        if (epi) {
            float bx = __ldg(bias + col), by = __ldg(bias + col + 1);
            lo.x = lo.x * rd0 + bx; lo.y = lo.y * rd0 + by;
            hi.x = hi.x * rd1 + bx; hi.y = hi.y * rd1 + by;
            lo.x = lo.x >= 0.f ? lo.x : 0.01f * lo.x;
            lo.y = lo.y >= 0.f ? lo.y : 0.01f * lo.y;
            hi.x = hi.x >= 0.f ? hi.x : 0.01f * hi.x;
            hi.y = hi.y >= 0.f ? hi.y : 0.01f * hi.y;
        }
        if (row0 < n) *(float2*)&out[(size_t)row0 * HID + col] = lo;
        if (row1 < n) *(float2*)&out[(size_t)row1 * HID + col] = hi;
    }
}

__global__ void __launch_bounds__(256) gemm_c_k(
    const float* __restrict__ A, const float* __restrict__ W,
    const float* __restrict__ rs_s, float* __restrict__ out, int n) {
    extern __shared__ float sm[];
    gemm_tile_tf32(A, W, rs_s, nullptr, nullptr, out, n, blockIdx.x * 64, true, false, sm);
}

#define NBB64 157
#define NBA64 313
__global__ void __launch_bounds__(256) gemm_ab_k(
    const float* __restrict__ aggB, const float* __restrict__ W_inst, const float* __restrict__ b_inst,
    const float* __restrict__ aggA, const float* __restrict__ W_svc, const float* __restrict__ b_svc,
    const float* __restrict__ rs, float* __restrict__ out) {
    extern __shared__ float sm[];
    if (blockIdx.x < NBB64) {
        gemm_tile_tf32(aggB, W_inst, nullptr, rs + OFF_B_D, b_inst,
                       out, NODE_N, blockIdx.x * 64, false, true, sm);
    } else {
        gemm_tile_tf32(aggA, W_svc, nullptr, rs + OFF_A_D, b_svc,
                       out + (size_t)(NODE_N + INST_N) * HID, SVC_N,
                       (blockIdx.x - NBB64) * 64, false, true, sm);
    }
}

// ============================================================================
// Host launch
// ============================================================================
extern "C" void kernel_launch(void* const* d_in, const int* in_sizes, int n_in,
                              void* d_out, int out_size) {
    const float* svc_feat  = (const float*)d_in[0];
    const float* inst_feat = (const float*)d_in[1];
    const float* node_feat = (const float*)d_in[2];
    const float* W_svc  = (const float*)d_in[3];
    const float* b_svc  = (const float*)d_in[4];
    const float* W_inst = (const float*)d_in[5];
    const float* b_inst = (const float*)d_in[6];
    const float* W_node = (const float*)d_in[7];
    const float* b_node = (const float*)d_in[8];
    const int* sc_src = (const int*)d_in[9];
    const int* sc_dst = (const int*)d_in[10];
    const int* in_src = (const int*)d_in[11];
    const int* in_dst = (const int*)d_in[12];
    const int* ni_src = (const int*)d_in[13];
    const int* ni_dst = (const int*)d_in[14];
    float* out = (float*)d_out;

    int E_sc = in_sizes[9];
    int E_in = in_sizes[11];
    int E_ni = in_sizes[13];
    int E_tot = E_sc + E_in + E_ni;

    int *cnt, *offA, *offB, *offC, *curA, *curB, *curC, *eA, *eB, *eC;
    float *rs, *aggA, *aggB, *hC;
    cudaGetSymbolAddress((void**)&cnt, g_cnt);
    cudaGetSymbolAddress((void**)&rs, g_rs);
    cudaGetSymbolAddress((void**)&offA, g_offA);
    cudaGetSymbolAddress((void**)&offB, g_offB);
    cudaGetSymbolAddress((void**)&offC, g_offC);
    cudaGetSymbolAddress((void**)&curA, g_curA);
    cudaGetSymbolAddress((void**)&curB, g_curB);
    cudaGetSymbolAddress((void**)&curC, g_curC);
    cudaGetSymbolAddress((void**)&eA, g_eA);
    cudaGetSymbolAddress((void**)&eB, g_eB);
    cudaGetSymbolAddress((void**)&eC, g_eC);
    cudaGetSymbolAddress((void**)&aggA, g_aggA);
    cudaGetSymbolAddress((void**)&aggB, g_aggB);
    cudaGetSymbolAddress((void**)&hC, g_hC);

    cudaFuncSetAttribute(gemm_c_k,  cudaFuncAttributeMaxDynamicSharedMemorySize, SMEM_GEMM);
    cudaFuncSetAttribute(gemm_ab_k, cudaFuncAttributeMaxDynamicSharedMemorySize, SMEM_GEMM);

    // 1) degrees (+ lookback flag reset); cnt arrives zeroed (load-time init
    //    on the first call, re-zeroed by scatter_all_k on every run)
    hist_all_k<<<(E_tot + 255) / 256, 256>>>(sc_src, sc_dst, E_sc,
                                             in_src, in_dst, E_in,
                                             ni_src, ni_dst, E_ni, cnt);

    // 2) fused scans + all rsqrt norms (single kernel, aggregate lookback)
    scanrs_k<<<NB_TOTAL + NB_SRC, 1024>>>(cnt, rs, offA, offB, offC,
                                          curA, curB, curC, E_sc, E_in, E_ni);

    // 3) conv C GEMM (needs only rs)
    gemm_c_k<<<(NODE_N + 63) / 64, 256, SMEM_GEMM>>>(node_feat, W_node, rs + OFF_C_S, hC, NODE_N);

    // 4) scatter into CSR (+ cnt re-zero for next replay)
    scatter_all_k<<<(E_tot + 255) / 256, 256>>>(sc_src, sc_dst, E_sc,
                                                in_src, in_dst, E_in,
                                                ni_src, ni_dst, E_ni,
                                                curA, curB, curC, eA, eB, eC, cnt);

    // 5) all three aggregations in one launch
    int total_warps = SVC_N + NODE_N + INST_N;
    agg_all_k<<<(total_warps * 32 + 255) / 256, 256>>>(
        svc_feat, inst_feat, hC, rs,
        offA, eA, offB, eB, offC, eC,
        b_node, aggA, aggB, out + (size_t)NODE_N * HID);

    // 6) combined A+B GEMM with fused epilogue
    gemm_ab_k<<<NBB64 + NBA64, 256, SMEM_GEMM>>>(aggB, W_inst, b_inst,
                                                 aggA, W_svc, b_svc, rs, out);
}